// round 16
// baseline (speedup 1.0000x reference)
#include <cuda_runtime.h>
#include <cuda_fp16.h>
#include <cstdint>
#include <cstddef>

#define HH 1024
#define TT 256
#define BB 64
#define BT (BB*TT)       /* 16384 */
#define G4 (4*HH)        /* 4096 */

/* fp16 GEMM tile constants (stride in halves) */
#define HSTR 40
#define L_ST (256*HSTR)             /* lstm1 stage halves (A128+B128) */
#define G_AT (128*HSTR)             /* gemm A region halves */
#define G_STG (384*HSTR)            /* gemm stage halves (A128+B256)  */

/* fused recurrence smem (bytes) — fragment-ordered slabs */
#define FRAG_H  32768               /* halves per slab (64KB)        */
#define F_G_B   (3*FRAG_H*2)        /* 196608: I2 exchange base      */
#define F_SMEM_B (F_G_B + 8192)     /* 204800 B                      */

/* fp16 scratch offsets (halves) */
#define X16_OFF  0u
#define W_L1A    4194304u
#define W_L1B    5242880u
#define W_L2A    9437184u
#define W_L2B    13631488u
#define W_M1     17825792u
#define W_M2     18874368u
#define W16_TOT  19398656u

// ------------------------- scratch (device globals) --------------------------
__device__ __align__(256) __half g_gates16[(size_t)BT * G4]; // fp16 xg1 scratch
__device__ __align__(256) __half g_w16[W16_TOT];
__device__ __align__(256) __half g_h1[(size_t)BT * HH];
__device__ __align__(256) __half g_h2[(size_t)BT * HH];
__device__ __align__(256) __half g_h1F[2 * 65536];
__device__ __align__(256) __half g_h2F[2 * 65536];
__device__ __align__(256) __half g_hlast[BB * HH];
__device__ __align__(256) __half g_z1[BB * HH];
__device__ __align__(256) __half g_z2[BB * (HH/2)];
__device__ unsigned g_cnt = 0;
__device__ unsigned g_sense = 0;

// ------------------------- helpers ------------------------------------------
__device__ __forceinline__ uint32_t ld_u32h(const __half* p) {
    return *(const uint32_t*)p;
}
__device__ __forceinline__ void mma_fp16(float c[4],
                                         uint32_t a0, uint32_t a1, uint32_t a2, uint32_t a3,
                                         uint32_t b0, uint32_t b1) {
    asm volatile(
        "mma.sync.aligned.m16n8k16.row.col.f32.f16.f16.f32 "
        "{%0,%1,%2,%3}, {%4,%5,%6,%7}, {%8,%9}, {%0,%1,%2,%3};"
        : "+f"(c[0]), "+f"(c[1]), "+f"(c[2]), "+f"(c[3])
        : "r"(a0), "r"(a1), "r"(a2), "r"(a3), "r"(b0), "r"(b1));
}
__device__ __forceinline__ void ldsm_x4(uint32_t& r0, uint32_t& r1,
                                        uint32_t& r2, uint32_t& r3, uint32_t sa) {
    asm volatile("ldmatrix.sync.aligned.m8n8.x4.shared.b16 {%0,%1,%2,%3}, [%4];"
                 : "=r"(r0), "=r"(r1), "=r"(r2), "=r"(r3) : "r"(sa));
}

// ---- fast activations: HW tanh.approx.f16x2 ----
__device__ __forceinline__ uint32_t tanh2_raw(uint32_t x) {
    uint32_t r;
    asm("tanh.approx.f16x2 %0, %1;" : "=r"(r) : "r"(x));
    return r;
}
__device__ __forceinline__ float2 sig2(float a, float b) {
    const __half2 xh = __floats2half2_rn(0.5f * a, 0.5f * b);
    uint32_t t = tanh2_raw(*(const uint32_t*)&xh);
    const float2 tf = __half22float2(*(const __half2*)&t);
    return make_float2(fmaf(0.5f, tf.x, 0.5f), fmaf(0.5f, tf.y, 0.5f));
}
__device__ __forceinline__ float2 tanh2f(float a, float b) {
    const __half2 xh = __floats2half2_rn(a, b);
    uint32_t t = tanh2_raw(*(const uint32_t*)&xh);
    return __half22float2(*(const __half2*)&t);
}

__device__ __forceinline__ void cp16(uint32_t dsh, const void* src) {
    asm volatile("cp.async.cg.shared.global [%0], [%1], 16;" :: "r"(dsh), "l"(src));
}
__device__ __forceinline__ void cp_commit() { asm volatile("cp.async.commit_group;"); }

// ---- scoped-atomic barrier primitives ----
__device__ __forceinline__ unsigned atom_add_acqrel(unsigned* p, unsigned v) {
    unsigned old;
    asm volatile("atom.add.acq_rel.gpu.u32 %0, [%1], %2;"
                 : "=r"(old) : "l"(p), "r"(v) : "memory");
    return old;
}
__device__ __forceinline__ unsigned ld_acquire(unsigned* p) {
    unsigned v;
    asm volatile("ld.acquire.gpu.u32 %0, [%1];" : "=r"(v) : "l"(p) : "memory");
    return v;
}

// =============================================================================
// fp32 -> fp16 conversion of xx + 6 weight matrices (one launch)
// =============================================================================
__global__ void convert_kernel(const float* __restrict__ xx,
                               const float* __restrict__ w0, const float* __restrict__ w1,
                               const float* __restrict__ w2, const float* __restrict__ w3,
                               const float* __restrict__ w4, const float* __restrict__ w5)
{
    const uint32_t i4 = blockIdx.x * blockDim.x + threadIdx.x;
    const float* src; uint32_t base4;
    if      (i4 < 1048576u) { src = xx; base4 = 0u; }
    else if (i4 < 1310720u) { src = w0; base4 = 1048576u; }
    else if (i4 < 2359296u) { src = w1; base4 = 1310720u; }
    else if (i4 < 3407872u) { src = w2; base4 = 2359296u; }
    else if (i4 < 4456448u) { src = w3; base4 = 3407872u; }
    else if (i4 < 4718592u) { src = w4; base4 = 4456448u; }
    else                    { src = w5; base4 = 4718592u; }
    const float4 v = ((const float4*)src)[i4 - base4];
    __half2* dst = (__half2*)(g_w16 + (size_t)i4 * 4);
    dst[0] = __floats2half2_rn(v.x, v.y);
    dst[1] = __floats2half2_rn(v.z, v.w);
}

// =============================================================================
// fp16 GEMM: C = A @ W^T (+bias, +ReLU). BM=128, BN=256, BK=32, 4-stage,
// ldmatrix.x4 fragment loads. (unchanged from R15)
// =============================================================================
template<int RELU, int HOUT>
__launch_bounds__(256, 1)
__global__ void gemm16_kernel(const __half* __restrict__ A, long long asr,
                              const __half* __restrict__ W,
                              const float* __restrict__ b1p, const float* __restrict__ b2p,
                              void* __restrict__ Cv, int M, int N, int K)
{
    extern __shared__ __half smh[];
    const int tid = threadIdx.x, lane = tid & 31, warp = tid >> 5;
    const int wm = warp >> 2, wn = warp & 3;
    const int g = lane >> 2, q = lane & 3;
    const int mb = blockIdx.y * 128, nb = blockIdx.x * 256;

    float acc[4][8][4];
#pragma unroll
    for (int a = 0; a < 4; a++)
#pragma unroll
        for (int b = 0; b < 8; b++)
#pragma unroll
            for (int c = 0; c < 4; c++) acc[a][b][c] = 0.0f;

    const uint32_t smb = (uint32_t)__cvta_generic_to_shared(smh);
    const __half* aptr[2]; uint32_t adst[2];
#pragma unroll
    for (int i = 0; i < 2; i++) {
        const int slot = tid + i * 256;
        const int row = slot >> 2, kc = (slot & 3) * 8;
        int gr = mb + row; if (gr > M - 1) gr = M - 1;
        aptr[i] = A + (size_t)gr * asr + kc;
        adst[i] = smb + (uint32_t)((row * HSTR + kc) * 2);
    }
    const __half* bptr[4]; uint32_t bdst[4];
#pragma unroll
    for (int i = 0; i < 4; i++) {
        const int slot = tid + i * 256;
        const int row = slot >> 2, kc = (slot & 3) * 8;
        bptr[i] = W + (size_t)(nb + row) * K + kc;
        bdst[i] = smb + (uint32_t)((G_AT + row * HSTR + kc) * 2);
    }

    const uint32_t alnb = (uint32_t)((((lane & 7) + ((lane >> 3) & 1) * 8) * HSTR
                                     + ((lane >> 4) & 1) * 8) * 2);
    const uint32_t blnb = (uint32_t)(((((lane >> 4) & 1) * 8 + (lane & 7)) * HSTR
                                     + ((lane >> 3) & 1) * 8) * 2);

    const int KT = K >> 5;
    auto issue = [&](int kt) {
        const uint32_t so = (uint32_t)((kt & 3) * G_STG * 2);
        const int koff = kt * 32;
#pragma unroll
        for (int i = 0; i < 2; i++) cp16(adst[i] + so, aptr[i] + koff);
#pragma unroll
        for (int i = 0; i < 4; i++) cp16(bdst[i] + so, bptr[i] + koff);
        cp_commit();
    };

    const int pre = KT < 3 ? KT : 3;
    for (int s = 0; s < pre; ++s) issue(s);

    for (int kt = 0; kt < KT; ++kt) {
        if (kt < KT - 2)       asm volatile("cp.async.wait_group 2;");
        else if (kt == KT - 2) asm volatile("cp.async.wait_group 1;");
        else                   asm volatile("cp.async.wait_group 0;");
        __syncthreads();
        if (kt + 3 < KT) issue(kt + 3);

        const uint32_t sb = smb + (uint32_t)((kt & 3) * G_STG * 2);
#pragma unroll
        for (int kk = 0; kk < 32; kk += 16) {
            uint32_t af[4][4], bfr[8][2];
#pragma unroll
            for (int mt = 0; mt < 4; mt++) {
                const uint32_t ad = sb + (uint32_t)(((wm * 64 + mt * 16) * HSTR + kk) * 2) + alnb;
                ldsm_x4(af[mt][0], af[mt][1], af[mt][2], af[mt][3], ad);
            }
#pragma unroll
            for (int np = 0; np < 4; np++) {
                const uint32_t bd = sb + (uint32_t)(((128 + wn * 64 + np * 16) * HSTR + kk) * 2) + blnb;
                ldsm_x4(bfr[np * 2][0], bfr[np * 2][1], bfr[np * 2 + 1][0], bfr[np * 2 + 1][1], bd);
            }
#pragma unroll
            for (int mt = 0; mt < 4; mt++)
#pragma unroll
                for (int nt = 0; nt < 8; nt++)
                    mma_fp16(acc[mt][nt], af[mt][0], af[mt][1], af[mt][2], af[mt][3],
                             bfr[nt][0], bfr[nt][1]);
        }
    }

#pragma unroll
    for (int mt = 0; mt < 4; mt++) {
#pragma unroll
        for (int nt = 0; nt < 8; nt++) {
            const int row0 = mb + wm * 64 + mt * 16 + g;
            const int col  = nb + wn * 64 + nt * 8 + 2 * q;
            const float b0v = (b1p ? b1p[col]     : 0.f) + (b2p ? b2p[col]     : 0.f);
            const float b1v = (b1p ? b1p[col + 1] : 0.f) + (b2p ? b2p[col + 1] : 0.f);
            float v0 = acc[mt][nt][0] + b0v, v1 = acc[mt][nt][1] + b1v;
            float v2 = acc[mt][nt][2] + b0v, v3 = acc[mt][nt][3] + b1v;
            if (RELU) {
                v0 = fmaxf(v0, 0.f); v1 = fmaxf(v1, 0.f);
                v2 = fmaxf(v2, 0.f); v3 = fmaxf(v3, 0.f);
            }
            if (HOUT) {
                __half* C = (__half*)Cv;
                if (row0 < M)     *(__half2*)(C + (size_t)row0 * N + col)       = __floats2half2_rn(v0, v1);
                if (row0 + 8 < M) *(__half2*)(C + (size_t)(row0 + 8) * N + col) = __floats2half2_rn(v2, v3);
            } else {
                float* C = (float*)Cv;
                if (row0 < M)     *(float2*)(C + (size_t)row0 * N + col)       = make_float2(v0, v1);
                if (row0 + 8 < M) *(float2*)(C + (size_t)(row0 + 8) * N + col) = make_float2(v2, v3);
            }
        }
    }
}

// =============================================================================
// fused lstm1 (fp16): ldmatrix loads (unchanged from R15)
// =============================================================================
__launch_bounds__(256, 1)
__global__ void lstm1_16_kernel(const __half* __restrict__ A, long long asr,
                                const __half* __restrict__ W,
                                const float* __restrict__ bih, const float* __restrict__ bhh,
                                __half* __restrict__ Hout, int M, int K)
{
    extern __shared__ __half smh[];
    const int tid = threadIdx.x, lane = tid & 31, warp = tid >> 5;
    const int wm = warp >> 2, wn = warp & 3;
    const int g = lane >> 2, q = lane & 3;
    const int mb = blockIdx.y * 128, nb = blockIdx.x * 128;

    const uint32_t smb = (uint32_t)__cvta_generic_to_shared(smh);

    const __half* aptr[2]; uint32_t adst[2];
#pragma unroll
    for (int i = 0; i < 2; i++) {
        const int slot = tid + i * 256;
        const int row = slot >> 2, kc = (slot & 3) * 8;
        int gr = mb + row; if (gr > M - 1) gr = M - 1;
        aptr[i] = A + (size_t)gr * asr + kc;
        adst[i] = smb + (uint32_t)((row * HSTR + kc) * 2);
    }
    uint32_t bdst[2]; int brow[2], bkc[2];
#pragma unroll
    for (int i = 0; i < 2; i++) {
        const int slot = tid + i * 256;
        brow[i] = slot >> 2; bkc[i] = (slot & 3) * 8;
        bdst[i] = smb + (uint32_t)(((128 + brow[i]) * HSTR + bkc[i]) * 2);
    }

    const uint32_t alnb = (uint32_t)((((lane & 7) + ((lane >> 3) & 1) * 8) * HSTR
                                     + ((lane >> 4) & 1) * 8) * 2);
    const uint32_t blnb = (uint32_t)(((((lane >> 4) & 1) * 8 + (lane & 7)) * HSTR
                                     + ((lane >> 3) & 1) * 8) * 2);

    const int KT = K >> 5;
    float keep[4][4][4];
    const int gset[3] = {0, 2, 3};

#pragma unroll 1
    for (int ph = 0; ph < 3; ++ph) {
        const int gate = gset[ph];
        const __half* Wb = W + ((size_t)(gate * HH + nb)) * K;

        float acc[4][4][4];
#pragma unroll
        for (int a = 0; a < 4; a++)
#pragma unroll
            for (int b = 0; b < 4; b++)
#pragma unroll
                for (int c = 0; c < 4; c++) acc[a][b][c] = 0.0f;

        auto issue = [&](int kt) {
            const int koff = kt * 32;
            const uint32_t so = (uint32_t)((kt & 3) * L_ST * 2);
#pragma unroll
            for (int i = 0; i < 2; i++) cp16(adst[i] + so, aptr[i] + koff);
#pragma unroll
            for (int i = 0; i < 2; i++) cp16(bdst[i] + so, Wb + (size_t)brow[i] * K + bkc[i] + koff);
            cp_commit();
        };

        const int pre = KT < 3 ? KT : 3;
        for (int s = 0; s < pre; ++s) issue(s);

        for (int kt = 0; kt < KT; ++kt) {
            if (kt < KT - 2)       asm volatile("cp.async.wait_group 2;");
            else if (kt == KT - 2) asm volatile("cp.async.wait_group 1;");
            else                   asm volatile("cp.async.wait_group 0;");
            __syncthreads();
            if (kt + 3 < KT) issue(kt + 3);

            const uint32_t sb = smb + (uint32_t)((kt & 3) * L_ST * 2);
#pragma unroll
            for (int kk = 0; kk < 32; kk += 16) {
                uint32_t af[4][4], bfr[4][2];
#pragma unroll
                for (int mt = 0; mt < 4; mt++) {
                    const uint32_t ad = sb + (uint32_t)(((wm * 64 + mt * 16) * HSTR + kk) * 2) + alnb;
                    ldsm_x4(af[mt][0], af[mt][1], af[mt][2], af[mt][3], ad);
                }
#pragma unroll
                for (int np = 0; np < 2; np++) {
                    const uint32_t bd = sb + (uint32_t)(((128 + wn * 32 + np * 16) * HSTR + kk) * 2) + blnb;
                    ldsm_x4(bfr[np * 2][0], bfr[np * 2][1], bfr[np * 2 + 1][0], bfr[np * 2 + 1][1], bd);
                }
#pragma unroll
                for (int mt = 0; mt < 4; mt++)
#pragma unroll
                    for (int nt = 0; nt < 4; nt++)
                        mma_fp16(acc[mt][nt], af[mt][0], af[mt][1], af[mt][2], af[mt][3],
                                 bfr[nt][0], bfr[nt][1]);
            }
        }
        __syncthreads();

#pragma unroll
        for (int mt = 0; mt < 4; mt++) {
#pragma unroll
            for (int nt = 0; nt < 4; nt++) {
                const int gcol = gate * HH + nb + wn * 32 + nt * 8 + 2 * q;
                const float b0 = bih[gcol] + bhh[gcol];
                const float b1 = bih[gcol + 1] + bhh[gcol + 1];
                const float u0 = acc[mt][nt][0] + b0, u1 = acc[mt][nt][1] + b1;
                const float u2 = acc[mt][nt][2] + b0, u3 = acc[mt][nt][3] + b1;
                if (ph == 0) {
                    const float2 sa = sig2(u0, u1), sb2 = sig2(u2, u3);
                    keep[mt][nt][0] = sa.x; keep[mt][nt][1] = sa.y;
                    keep[mt][nt][2] = sb2.x; keep[mt][nt][3] = sb2.y;
                } else if (ph == 1) {
                    const float2 ta = tanh2f(u0, u1), tb = tanh2f(u2, u3);
                    keep[mt][nt][0] *= ta.x; keep[mt][nt][1] *= ta.y;
                    keep[mt][nt][2] *= tb.x; keep[mt][nt][3] *= tb.y;
                } else {
                    const float2 sa = sig2(u0, u1), sb2 = sig2(u2, u3);
                    const float2 ka = tanh2f(keep[mt][nt][0], keep[mt][nt][1]);
                    const float2 kb = tanh2f(keep[mt][nt][2], keep[mt][nt][3]);
                    const int row0 = mb + wm * 64 + mt * 16 + g;
                    const int colh = nb + wn * 32 + nt * 8 + 2 * q;
                    if (row0 < M)
                        *(__half2*)(Hout + (size_t)row0 * HH + colh) =
                            __floats2half2_rn(sa.x * ka.x, sa.y * ka.y);
                    if (row0 + 8 < M)
                        *(__half2*)(Hout + (size_t)(row0 + 8) * HH + colh) =
                            __floats2half2_rn(sb2.x * kb.x, sb2.y * kb.y);
                }
            }
        }
    }
}

// ------------------------- 128-CTA grid barrier (acq_rel) ---------------------
__device__ __forceinline__ void grid_bar()
{
    __syncthreads();
    if (threadIdx.x == 0) {
        const unsigned gen = ld_acquire(&g_sense);
        const unsigned arrived = atom_add_acqrel(&g_cnt, 1u);
        if (arrived == 127u) {
            g_cnt = 0;
            atom_add_acqrel(&g_sense, 1u);
        } else {
            while (ld_acquire(&g_sense) == gen) { __nanosleep(16); }
        }
    }
    __syncthreads();
}

// =============================================================================
// FUSED DUAL-LAYER RECURRENCE — fragment-ordered weight slabs (LDS.128, retry
// with ring-8 so registers don't spill) + register gates + f16x2 activations.
//
// Slab layout (halves): word w = kk*256 + lane*8 + h*4 + nt holds packed
// (W[n][k],W[n][k+1]) with n = nt*8+(lane>>2), k = kk*16+2(lane&3)+8h.
// Per kk each mma unit: 2 x LDS.128 (uint4 = all 4 nt for one h).
// =============================================================================
__launch_bounds__(256, 1)
__global__ void fused_recur_kernel(const __half* __restrict__ xg1,  // [BT,4096] fp16
                                   const float* __restrict__ Whh1,
                                   const float* __restrict__ Wih2,
                                   const float* __restrict__ Whh2,
                                   const float* __restrict__ b2i,
                                   const float* __restrict__ b2h,
                                   __half* __restrict__ hlast,
                                   __half* __restrict__ h1F,
                                   __half* __restrict__ h2F)
{
    extern __shared__ char smc[];
    __half* slab = (__half*)smc;                 // 3 x FRAG_H halves
    float*  PIg  = (float*)(smc + F_G_B);        // [4 warps][32 lanes][16]

    const int tid = threadIdx.x, lane = tid & 31, warp = tid >> 5;
    const int g = lane >> 2, q = lane & 3;
    const int n0 = blockIdx.x * 8;

    // ---- build fragment-ordered weight slabs ----
#pragma unroll 1
    for (int m = 0; m < 3; m++) {
        const float* Wsrc = (m == 0) ? Whh1 : (m == 1) ? Wih2 : Whh2;
        __half* dst = slab + m * FRAG_H;
#pragma unroll 1
        for (int w = tid; w < 16384; w += 256) {
            const int kk = w >> 8, rem = w & 255;
            const int lw = rem >> 3, h = (rem >> 2) & 1, nt = rem & 3;
            const int n = nt * 8 + (lw >> 2);
            const int k = kk * 16 + 2 * (lw & 3) + 8 * h;
            const int r = (n >> 3) * HH + n0 + (n & 7);
            const float2 v = *(const float2*)(Wsrc + (size_t)r * HH + k);
            *(__half2*)(dst + (size_t)w * 2) = __floats2half2_rn(v.x, v.y);
        }
    }
    __syncthreads();

    const int mq = warp & 3;
    const int isL = (warp < 4);
    const __half* fA = slab + (isL ? 0 : 2) * FRAG_H;   // Whh1 or Whh2
    const __half* fB = slab + FRAG_H;                   // Wih2 (warps 0-3)

    const int row_a = mq * 16 + g, row_b = row_a + 8;
    const int colj = n0 + 2 * q;
    const size_t st_off = ((size_t)(mq * 64 + (blockIdx.x >> 1)) * 32 + lane) * 8
                          + 4 * (size_t)(blockIdx.x & 1);

    float bias_[4][2];
    if (!isL) {
#pragma unroll
        for (int gg = 0; gg < 4; gg++) {
            const float2 bi = *(const float2*)(b2i + gg * HH + colj);
            const float2 bh = *(const float2*)(b2h + gg * HH + colj);
            bias_[gg][0] = bi.x + bh.x;
            bias_[gg][1] = bi.y + bh.y;
        }
    }

    float c00 = 0.f, c01 = 0.f, c10 = 0.f, c11 = 0.f;

#pragma unroll 1
    for (int s = 0; s <= TT; s++) {
        float xgv[4][4];
        if (isL && s < TT) {
            const size_t ba = ((size_t)(row_a * TT + s)) * G4 + colj;
            const size_t bb = ((size_t)(row_b * TT + s)) * G4 + colj;
#pragma unroll
            for (int gg = 0; gg < 4; gg++) {
                const float2 fa = __half22float2(*(const __half2*)(xg1 + ba + gg * 1024));
                const float2 fb = __half22float2(*(const __half2*)(xg1 + bb + gg * 1024));
                xgv[gg][0] = fa.x; xgv[gg][1] = fa.y;
                xgv[gg][2] = fb.x; xgv[gg][3] = fb.y;
            }
        }

        float accA[4][4], accB[4][4];
#pragma unroll
        for (int nt = 0; nt < 4; nt++)
#pragma unroll
            for (int cc = 0; cc < 4; cc++) { accA[nt][cc] = 0.f; accB[nt][cc] = 0.f; }

        const int doA = isL ? (s >= 1) : (s >= 2);
        if (doA) {
            const int par = (s - 1) & 1;
            const float4* Ab = (const float4*)((isL ? h1F : h2F) + (size_t)par * 65536)
                               + (size_t)mq * 64 * 32 + lane;

            float4 buf[8];
#pragma unroll
            for (int p = 0; p < 8; p++) buf[p] = __ldcg(Ab + p * 32);

#pragma unroll 8
            for (int kk = 0; kk < 64; ++kk) {
                const float4 f = buf[kk & 7];
                if (kk < 56) buf[kk & 7] = __ldcg(Ab + (kk + 8) * 32);
                const uint32_t a0 = __float_as_uint(f.x), a1 = __float_as_uint(f.y);
                const uint32_t a2 = __float_as_uint(f.z), a3 = __float_as_uint(f.w);

                const int fo = kk * 512 + lane * 16;   // halves
                const uint4 wA0 = *(const uint4*)(fA + fo);
                const uint4 wA1 = *(const uint4*)(fA + fo + 8);
                mma_fp16(accA[0], a0, a1, a2, a3, wA0.x, wA1.x);
                mma_fp16(accA[1], a0, a1, a2, a3, wA0.y, wA1.y);
                mma_fp16(accA[2], a0, a1, a2, a3, wA0.z, wA1.z);
                mma_fp16(accA[3], a0, a1, a2, a3, wA0.w, wA1.w);
                if (isL) {
                    const uint4 wB0 = *(const uint4*)(fB + fo);
                    const uint4 wB1 = *(const uint4*)(fB + fo + 8);
                    mma_fp16(accB[0], a0, a1, a2, a3, wB0.x, wB1.x);
                    mma_fp16(accB[1], a0, a1, a2, a3, wB0.y, wB1.y);
                    mma_fp16(accB[2], a0, a1, a2, a3, wB0.z, wB1.z);
                    mma_fp16(accB[3], a0, a1, a2, a3, wB0.w, wB1.w);
                }
            }

            if (isL) {
                float* pw = PIg + (mq * 32 + lane) * 16;
#pragma unroll
                for (int nt = 0; nt < 4; nt++)
                    *(float4*)(pw + nt * 4) = make_float4(accB[nt][0], accB[nt][1],
                                                          accB[nt][2], accB[nt][3]);
            }
        }

        if (isL && s < TT) {
            const float gi0 = xgv[0][0] + accA[0][0], gi1 = xgv[0][1] + accA[0][1];
            const float gi2 = xgv[0][2] + accA[0][2], gi3 = xgv[0][3] + accA[0][3];
            const float gf0 = xgv[1][0] + accA[1][0], gf1 = xgv[1][1] + accA[1][1];
            const float gf2 = xgv[1][2] + accA[1][2], gf3 = xgv[1][3] + accA[1][3];
            const float gG0 = xgv[2][0] + accA[2][0], gG1 = xgv[2][1] + accA[2][1];
            const float gG2 = xgv[2][2] + accA[2][2], gG3 = xgv[2][3] + accA[2][3];
            const float go0 = xgv[3][0] + accA[3][0], go1 = xgv[3][1] + accA[3][1];
            const float go2 = xgv[3][2] + accA[3][2], go3 = xgv[3][3] + accA[3][3];
            const float2 si01 = sig2(gi0, gi1), si23 = sig2(gi2, gi3);
            const float2 sf01 = sig2(gf0, gf1), sf23 = sig2(gf2, gf3);
            const float2 tg01 = tanh2f(gG0, gG1), tg23 = tanh2f(gG2, gG3);
            const float2 so01 = sig2(go0, go1), so23 = sig2(go2, go3);
            c00 = fmaf(sf01.x, c00, si01.x * tg01.x);
            c01 = fmaf(sf01.y, c01, si01.y * tg01.y);
            c10 = fmaf(sf23.x, c10, si23.x * tg23.x);
            c11 = fmaf(sf23.y, c11, si23.y * tg23.y);
            const float2 tc01 = tanh2f(c00, c01), tc23 = tanh2f(c10, c11);
            const __half2 lo = __floats2half2_rn(so01.x * tc01.x, so01.y * tc01.y);
            const __half2 hi = __floats2half2_rn(so23.x * tc23.x, so23.y * tc23.y);
            uint2 val;
            val.x = *(const uint32_t*)&lo;
            val.y = *(const uint32_t*)&hi;
            *(uint2*)(h1F + (size_t)(s & 1) * 65536 + st_off) = val;
        }

        __syncthreads();

        if (!isL && s >= 1) {
            const float* pw = PIg + (mq * 32 + lane) * 16;
            float pi[4][4];
#pragma unroll
            for (int nt = 0; nt < 4; nt++) {
                const float4 v = *(const float4*)(pw + nt * 4);
                pi[nt][0] = v.x; pi[nt][1] = v.y; pi[nt][2] = v.z; pi[nt][3] = v.w;
            }
            const float gi0 = pi[0][0] + bias_[0][0] + accA[0][0];
            const float gi1 = pi[0][1] + bias_[0][1] + accA[0][1];
            const float gi2 = pi[0][2] + bias_[0][0] + accA[0][2];
            const float gi3 = pi[0][3] + bias_[0][1] + accA[0][3];
            const float gf0 = pi[1][0] + bias_[1][0] + accA[1][0];
            const float gf1 = pi[1][1] + bias_[1][1] + accA[1][1];
            const float gf2 = pi[1][2] + bias_[1][0] + accA[1][2];
            const float gf3 = pi[1][3] + bias_[1][1] + accA[1][3];
            const float gG0 = pi[2][0] + bias_[2][0] + accA[2][0];
            const float gG1 = pi[2][1] + bias_[2][1] + accA[2][1];
            const float gG2 = pi[2][2] + bias_[2][0] + accA[2][2];
            const float gG3 = pi[2][3] + bias_[2][1] + accA[2][3];
            const float go0 = pi[3][0] + bias_[3][0] + accA[3][0];
            const float go1 = pi[3][1] + bias_[3][1] + accA[3][1];
            const float go2 = pi[3][2] + bias_[3][0] + accA[3][2];
            const float go3 = pi[3][3] + bias_[3][1] + accA[3][3];
            const float2 si01 = sig2(gi0, gi1), si23 = sig2(gi2, gi3);
            const float2 sf01 = sig2(gf0, gf1), sf23 = sig2(gf2, gf3);
            const float2 tg01 = tanh2f(gG0, gG1), tg23 = tanh2f(gG2, gG3);
            const float2 so01 = sig2(go0, go1), so23 = sig2(go2, go3);
            c00 = fmaf(sf01.x, c00, si01.x * tg01.x);
            c01 = fmaf(sf01.y, c01, si01.y * tg01.y);
            c10 = fmaf(sf23.x, c10, si23.x * tg23.x);
            c11 = fmaf(sf23.y, c11, si23.y * tg23.y);
            const float2 tc01 = tanh2f(c00, c01), tc23 = tanh2f(c10, c11);
            const float h0 = so01.x * tc01.x, h1 = so01.y * tc01.y;
            const float h2 = so23.x * tc23.x, h3 = so23.y * tc23.y;
            if (s < TT) {
                const __half2 lo = __floats2half2_rn(h0, h1);
                const __half2 hi = __floats2half2_rn(h2, h3);
                uint2 val;
                val.x = *(const uint32_t*)&lo;
                val.y = *(const uint32_t*)&hi;
                *(uint2*)(h2F + (size_t)(s & 1) * 65536 + st_off) = val;
            } else {
                *(__half2*)(hlast + (size_t)row_a * HH + colj) = __floats2half2_rn(h0, h1);
                *(__half2*)(hlast + (size_t)row_b * HH + colj) = __floats2half2_rn(h2, h3);
            }
        }

        if (s < TT) grid_bar();
    }
}

// ------------------------- final MLP layer 3 ---------------------------------
__global__ void mlp3_kernel(const __half* __restrict__ z2, const float* __restrict__ W3,
                            const float* __restrict__ b3, float* __restrict__ out)
{
    __shared__ float red[8];
    const int b = blockIdx.x;
    float s = 0.f;
    for (int k = threadIdx.x; k < 512; k += 256)
        s += __half2float(z2[b * 512 + k]) * W3[k];
#pragma unroll
    for (int o = 16; o; o >>= 1) s += __shfl_down_sync(0xffffffffu, s, o);
    if ((threadIdx.x & 31) == 0) red[threadIdx.x >> 5] = s;
    __syncthreads();
    if (threadIdx.x < 8) {
        s = red[threadIdx.x];
#pragma unroll
        for (int o = 4; o; o >>= 1) s += __shfl_down_sync(0xffu, s, o);
        if (threadIdx.x == 0) out[b] = s + b3[0];
    }
}

// ------------------------- launcher ------------------------------------------
extern "C" void kernel_launch(void* const* d_in, const int* in_sizes, int n_in,
                              void* d_out, int out_size)
{
    const float* xx       = (const float*)d_in[0];
    const float* l1_Wih0  = (const float*)d_in[1];
    const float* l1_bih0  = (const float*)d_in[2];
    const float* l1_bhh0  = (const float*)d_in[3];
    const float* l1_Wih1  = (const float*)d_in[4];
    const float* l1_bih1  = (const float*)d_in[5];
    const float* l1_bhh1  = (const float*)d_in[6];
    const float* l2_Wih0  = (const float*)d_in[7];
    const float* l2_Whh0  = (const float*)d_in[8];
    const float* l2_bih0  = (const float*)d_in[9];
    const float* l2_bhh0  = (const float*)d_in[10];
    const float* l2_Wih1  = (const float*)d_in[11];
    const float* l2_Whh1  = (const float*)d_in[12];
    const float* l2_bih1  = (const float*)d_in[13];
    const float* l2_bhh1  = (const float*)d_in[14];
    const float* mlp_W1   = (const float*)d_in[15];
    const float* mlp_b1   = (const float*)d_in[16];
    const float* mlp_W2   = (const float*)d_in[17];
    const float* mlp_b2   = (const float*)d_in[18];
    const float* mlp_W3   = (const float*)d_in[19];
    const float* mlp_b3   = (const float*)d_in[20];
    float* out = (float*)d_out;

    void* p;
    cudaGetSymbolAddress(&p, g_gates16); __half* gates16 = (__half*)p;
    cudaGetSymbolAddress(&p, g_w16);   __half* w16   = (__half*)p;
    cudaGetSymbolAddress(&p, g_h1);    __half* h1    = (__half*)p;
    cudaGetSymbolAddress(&p, g_h2);    __half* h2    = (__half*)p;
    cudaGetSymbolAddress(&p, g_h1F);   __half* h1F   = (__half*)p;
    cudaGetSymbolAddress(&p, g_h2F);   __half* h2F   = (__half*)p;
    cudaGetSymbolAddress(&p, g_hlast); __half* hlast = (__half*)p;
    cudaGetSymbolAddress(&p, g_z1);    __half* z1    = (__half*)p;
    cudaGetSymbolAddress(&p, g_z2);    __half* z2    = (__half*)p;

    const int lstm1_smem = 4 * L_ST * 2;     // 81920 B
    const int gemm_smem  = 4 * G_STG * 2;    // 122880 B
    const int fused_smem = F_SMEM_B;         // 204800 B
    cudaFuncSetAttribute((const void*)gemm16_kernel<0,1>, cudaFuncAttributeMaxDynamicSharedMemorySize, gemm_smem);
    cudaFuncSetAttribute((const void*)gemm16_kernel<1,1>, cudaFuncAttributeMaxDynamicSharedMemorySize, gemm_smem);
    cudaFuncSetAttribute((const void*)lstm1_16_kernel,    cudaFuncAttributeMaxDynamicSharedMemorySize, lstm1_smem);
    cudaFuncSetAttribute((const void*)fused_recur_kernel, cudaFuncAttributeMaxDynamicSharedMemorySize, fused_smem);

    const dim3 blk(256);

    // [0] fp32 -> fp16 (xx + 6 weight matrices)
    convert_kernel<<<4849664 / 256, blk>>>(xx, l1_Wih0, l1_Wih1, l2_Wih0, l2_Wih1, mlp_W1, mlp_W2);

    // [1][2] lstm1 (fused, f gate skipped)
    lstm1_16_kernel<<<dim3(HH / 128, BT / 128), blk, lstm1_smem>>>(w16 + X16_OFF, 256, w16 + W_L1A,
                                                                   l1_bih0, l1_bhh0, h1, BT, 256);
    lstm1_16_kernel<<<dim3(HH / 128, BT / 128), blk, lstm1_smem>>>(h1, HH, w16 + W_L1B,
                                                                   l1_bih1, l1_bhh1, h2, BT, HH);

    // [3] lstm2 layer-0 xg GEMM (fp16 out) ; [4] fused dual recurrence
    gemm16_kernel<0,1><<<dim3(G4 / 256, BT / 128), blk, gemm_smem>>>(h2, HH, w16 + W_L2A,
                                                                     l2_bih0, l2_bhh0,
                                                                     gates16, BT, G4, HH);
    fused_recur_kernel<<<128, blk, fused_smem>>>(gates16, l2_Whh0, l2_Wih1, l2_Whh1,
                                                 l2_bih1, l2_bhh1, hlast, h1F, h2F);

    // [5][6][7] MLP on h2(255)
    gemm16_kernel<1,1><<<dim3(HH / 256, 1), blk, gemm_smem>>>(hlast, HH, w16 + W_M1, mlp_b1, nullptr,
                                                              z1, BB, HH, HH);
    gemm16_kernel<1,1><<<dim3((HH / 2) / 256, 1), blk, gemm_smem>>>(z1, HH, w16 + W_M2, mlp_b2, nullptr,
                                                                    z2, BB, HH / 2, HH);
    mlp3_kernel<<<BB, blk>>>(z2, mlp_W3, mlp_b3, out);
}

// round 17
// speedup vs baseline: 1.0086x; 1.0086x over previous
#include <cuda_runtime.h>
#include <cuda_fp16.h>
#include <cstdint>
#include <cstddef>

#define HH 1024
#define TT 256
#define BB 64
#define BT (BB*TT)       /* 16384 */
#define G4 (4*HH)        /* 4096 */

/* fp16 GEMM tile constants (stride in halves) */
#define HSTR 40
#define L_ST (256*HSTR)             /* 128x128 tile stage halves (A128+B128) */

/* fused recurrence smem (bytes) */
#define FW_STR 1032                 /* slab row stride (halves)      */
#define F_G_B  (3*32*FW_STR*2)      /* 198144: I2 exchange base      */
#define F_SMEM_B (F_G_B + 8192)     /* 206336 B                      */

/* fp16 scratch offsets (halves) */
#define X16_OFF  0u
#define W_L1A    4194304u
#define W_L1B    5242880u
#define W_L2A    9437184u
#define W_L2B    13631488u
#define W_M1     17825792u
#define W_M2     18874368u
#define W16_TOT  19398656u

// ------------------------- scratch (device globals) --------------------------
__device__ __align__(256) __half g_gates16[(size_t)BT * G4]; // fp16 xg1 scratch
__device__ __align__(256) __half g_w16[W16_TOT];
__device__ __align__(256) __half g_h1[(size_t)BT * HH];
__device__ __align__(256) __half g_h2[(size_t)BT * HH];
__device__ __align__(256) __half g_h1F[2 * 65536];
__device__ __align__(256) __half g_h2F[2 * 65536];
__device__ __align__(256) __half g_hlast[BB * HH];
__device__ __align__(256) __half g_z1[BB * HH];
__device__ __align__(256) __half g_z2[BB * (HH/2)];
__device__ unsigned g_cnt = 0;
__device__ unsigned g_sense = 0;

// ------------------------- helpers ------------------------------------------
__device__ __forceinline__ uint32_t ld_u32h(const __half* p) {
    return *(const uint32_t*)p;
}
__device__ __forceinline__ void mma_fp16(float c[4],
                                         uint32_t a0, uint32_t a1, uint32_t a2, uint32_t a3,
                                         uint32_t b0, uint32_t b1) {
    asm volatile(
        "mma.sync.aligned.m16n8k16.row.col.f32.f16.f16.f32 "
        "{%0,%1,%2,%3}, {%4,%5,%6,%7}, {%8,%9}, {%0,%1,%2,%3};"
        : "+f"(c[0]), "+f"(c[1]), "+f"(c[2]), "+f"(c[3])
        : "r"(a0), "r"(a1), "r"(a2), "r"(a3), "r"(b0), "r"(b1));
}
__device__ __forceinline__ void ldsm_x4(uint32_t& r0, uint32_t& r1,
                                        uint32_t& r2, uint32_t& r3, uint32_t sa) {
    asm volatile("ldmatrix.sync.aligned.m8n8.x4.shared.b16 {%0,%1,%2,%3}, [%4];"
                 : "=r"(r0), "=r"(r1), "=r"(r2), "=r"(r3) : "r"(sa));
}

// ---- fast activations: HW tanh.approx.f16x2 ----
__device__ __forceinline__ uint32_t tanh2_raw(uint32_t x) {
    uint32_t r;
    asm("tanh.approx.f16x2 %0, %1;" : "=r"(r) : "r"(x));
    return r;
}
__device__ __forceinline__ float2 sig2(float a, float b) {
    const __half2 xh = __floats2half2_rn(0.5f * a, 0.5f * b);
    uint32_t t = tanh2_raw(*(const uint32_t*)&xh);
    const float2 tf = __half22float2(*(const __half2*)&t);
    return make_float2(fmaf(0.5f, tf.x, 0.5f), fmaf(0.5f, tf.y, 0.5f));
}
__device__ __forceinline__ float2 tanh2f(float a, float b) {
    const __half2 xh = __floats2half2_rn(a, b);
    uint32_t t = tanh2_raw(*(const uint32_t*)&xh);
    return __half22float2(*(const __half2*)&t);
}

__device__ __forceinline__ void cp16(uint32_t dsh, const void* src) {
    asm volatile("cp.async.cg.shared.global [%0], [%1], 16;" :: "r"(dsh), "l"(src));
}
__device__ __forceinline__ void cp_commit() { asm volatile("cp.async.commit_group;"); }

// ---- scoped-atomic barrier primitives ----
__device__ __forceinline__ unsigned atom_add_acqrel(unsigned* p, unsigned v) {
    unsigned old;
    asm volatile("atom.add.acq_rel.gpu.u32 %0, [%1], %2;"
                 : "=r"(old) : "l"(p), "r"(v) : "memory");
    return old;
}
__device__ __forceinline__ unsigned ld_acquire(unsigned* p) {
    unsigned v;
    asm volatile("ld.acquire.gpu.u32 %0, [%1];" : "=r"(v) : "l"(p) : "memory");
    return v;
}

// =============================================================================
// fp32 -> fp16 conversion of xx + 6 weight matrices (one launch)
// =============================================================================
__global__ void convert_kernel(const float* __restrict__ xx,
                               const float* __restrict__ w0, const float* __restrict__ w1,
                               const float* __restrict__ w2, const float* __restrict__ w3,
                               const float* __restrict__ w4, const float* __restrict__ w5)
{
    const uint32_t i4 = blockIdx.x * blockDim.x + threadIdx.x;
    const float* src; uint32_t base4;
    if      (i4 < 1048576u) { src = xx; base4 = 0u; }
    else if (i4 < 1310720u) { src = w0; base4 = 1048576u; }
    else if (i4 < 2359296u) { src = w1; base4 = 1310720u; }
    else if (i4 < 3407872u) { src = w2; base4 = 2359296u; }
    else if (i4 < 4456448u) { src = w3; base4 = 3407872u; }
    else if (i4 < 4718592u) { src = w4; base4 = 4456448u; }
    else                    { src = w5; base4 = 4718592u; }
    const float4 v = ((const float4*)src)[i4 - base4];
    __half2* dst = (__half2*)(g_w16 + (size_t)i4 * 4);
    dst[0] = __floats2half2_rn(v.x, v.y);
    dst[1] = __floats2half2_rn(v.z, v.w);
}

// =============================================================================
// fp16 GEMM (2 CTA/SM): C = A @ W^T (+bias,+ReLU). BM=128, BN=128, BK=32,
// 3-stage cp.async, ldmatrix loads, warp tile 64x32, acc 64 regs.
// =============================================================================
template<int RELU, int HOUT>
__launch_bounds__(256, 2)
__global__ void gemm128_kernel(const __half* __restrict__ A, long long asr,
                               const __half* __restrict__ W,
                               const float* __restrict__ b1p, const float* __restrict__ b2p,
                               void* __restrict__ Cv, int M, int N, int K)
{
    extern __shared__ __half smh[];
    const int tid = threadIdx.x, lane = tid & 31, warp = tid >> 5;
    const int wm = warp >> 2, wn = warp & 3;
    const int g = lane >> 2, q = lane & 3;
    const int mb = blockIdx.y * 128, nb = blockIdx.x * 128;

    float acc[4][4][4];
#pragma unroll
    for (int a = 0; a < 4; a++)
#pragma unroll
        for (int b = 0; b < 4; b++)
#pragma unroll
            for (int c = 0; c < 4; c++) acc[a][b][c] = 0.0f;

    const uint32_t smb = (uint32_t)__cvta_generic_to_shared(smh);
    const __half* aptr[2]; uint32_t adst[2];
#pragma unroll
    for (int i = 0; i < 2; i++) {
        const int slot = tid + i * 256;
        const int row = slot >> 2, kc = (slot & 3) * 8;
        int gr = mb + row; if (gr > M - 1) gr = M - 1;
        aptr[i] = A + (size_t)gr * asr + kc;
        adst[i] = smb + (uint32_t)((row * HSTR + kc) * 2);
    }
    const __half* bptr[2]; uint32_t bdst[2];
#pragma unroll
    for (int i = 0; i < 2; i++) {
        const int slot = tid + i * 256;
        const int row = slot >> 2, kc = (slot & 3) * 8;
        bptr[i] = W + (size_t)(nb + row) * K + kc;
        bdst[i] = smb + (uint32_t)(((128 + row) * HSTR + kc) * 2);
    }

    const uint32_t alnb = (uint32_t)((((lane & 7) + ((lane >> 3) & 1) * 8) * HSTR
                                     + ((lane >> 4) & 1) * 8) * 2);
    const uint32_t blnb = (uint32_t)(((((lane >> 4) & 1) * 8 + (lane & 7)) * HSTR
                                     + ((lane >> 3) & 1) * 8) * 2);

    const int KT = K >> 5;
    auto issue = [&](int kt) {
        const uint32_t so = (uint32_t)((kt % 3) * L_ST * 2);
        const int koff = kt * 32;
#pragma unroll
        for (int i = 0; i < 2; i++) cp16(adst[i] + so, aptr[i] + koff);
#pragma unroll
        for (int i = 0; i < 2; i++) cp16(bdst[i] + so, bptr[i] + koff);
        cp_commit();
    };

    issue(0); if (KT > 1) issue(1);

    for (int kt = 0; kt < KT; ++kt) {
        if (kt < KT - 1) asm volatile("cp.async.wait_group 1;");
        else             asm volatile("cp.async.wait_group 0;");
        __syncthreads();
        if (kt + 2 < KT) issue(kt + 2);

        const uint32_t sb = smb + (uint32_t)((kt % 3) * L_ST * 2);
#pragma unroll
        for (int kk = 0; kk < 32; kk += 16) {
            uint32_t af[4][4], bfr[4][2];
#pragma unroll
            for (int mt = 0; mt < 4; mt++) {
                const uint32_t ad = sb + (uint32_t)(((wm * 64 + mt * 16) * HSTR + kk) * 2) + alnb;
                ldsm_x4(af[mt][0], af[mt][1], af[mt][2], af[mt][3], ad);
            }
            {
                const uint32_t bd = sb + (uint32_t)(((128 + wn * 32) * HSTR + kk) * 2) + blnb;
                ldsm_x4(bfr[0][0], bfr[0][1], bfr[1][0], bfr[1][1], bd);
                const uint32_t bd2 = bd + (uint32_t)(16 * HSTR * 2);
                ldsm_x4(bfr[2][0], bfr[2][1], bfr[3][0], bfr[3][1], bd2);
            }
#pragma unroll
            for (int mt = 0; mt < 4; mt++)
#pragma unroll
                for (int nt = 0; nt < 4; nt++)
                    mma_fp16(acc[mt][nt], af[mt][0], af[mt][1], af[mt][2], af[mt][3],
                             bfr[nt][0], bfr[nt][1]);
        }
    }

#pragma unroll
    for (int mt = 0; mt < 4; mt++) {
#pragma unroll
        for (int nt = 0; nt < 4; nt++) {
            const int row0 = mb + wm * 64 + mt * 16 + g;
            const int col  = nb + wn * 32 + nt * 8 + 2 * q;
            const float b0v = (b1p ? b1p[col]     : 0.f) + (b2p ? b2p[col]     : 0.f);
            const float b1v = (b1p ? b1p[col + 1] : 0.f) + (b2p ? b2p[col + 1] : 0.f);
            float v0 = acc[mt][nt][0] + b0v, v1 = acc[mt][nt][1] + b1v;
            float v2 = acc[mt][nt][2] + b0v, v3 = acc[mt][nt][3] + b1v;
            if (RELU) {
                v0 = fmaxf(v0, 0.f); v1 = fmaxf(v1, 0.f);
                v2 = fmaxf(v2, 0.f); v3 = fmaxf(v3, 0.f);
            }
            if (HOUT) {
                __half* C = (__half*)Cv;
                if (row0 < M)     *(__half2*)(C + (size_t)row0 * N + col)       = __floats2half2_rn(v0, v1);
                if (row0 + 8 < M) *(__half2*)(C + (size_t)(row0 + 8) * N + col) = __floats2half2_rn(v2, v3);
            } else {
                float* C = (float*)Cv;
                if (row0 < M)     *(float2*)(C + (size_t)row0 * N + col)       = make_float2(v0, v1);
                if (row0 + 8 < M) *(float2*)(C + (size_t)(row0 + 8) * N + col) = make_float2(v2, v3);
            }
        }
    }
}

// =============================================================================
// fused lstm1 (fp16): ldmatrix loads, 4-stage (unchanged from R15)
// =============================================================================
#define L4_ST (256*HSTR)
__launch_bounds__(256, 1)
__global__ void lstm1_16_kernel(const __half* __restrict__ A, long long asr,
                                const __half* __restrict__ W,
                                const float* __restrict__ bih, const float* __restrict__ bhh,
                                __half* __restrict__ Hout, int M, int K)
{
    extern __shared__ __half smh[];
    const int tid = threadIdx.x, lane = tid & 31, warp = tid >> 5;
    const int wm = warp >> 2, wn = warp & 3;
    const int g = lane >> 2, q = lane & 3;
    const int mb = blockIdx.y * 128, nb = blockIdx.x * 128;

    const uint32_t smb = (uint32_t)__cvta_generic_to_shared(smh);

    const __half* aptr[2]; uint32_t adst[2];
#pragma unroll
    for (int i = 0; i < 2; i++) {
        const int slot = tid + i * 256;
        const int row = slot >> 2, kc = (slot & 3) * 8;
        int gr = mb + row; if (gr > M - 1) gr = M - 1;
        aptr[i] = A + (size_t)gr * asr + kc;
        adst[i] = smb + (uint32_t)((row * HSTR + kc) * 2);
    }
    uint32_t bdst[2]; int brow[2], bkc[2];
#pragma unroll
    for (int i = 0; i < 2; i++) {
        const int slot = tid + i * 256;
        brow[i] = slot >> 2; bkc[i] = (slot & 3) * 8;
        bdst[i] = smb + (uint32_t)(((128 + brow[i]) * HSTR + bkc[i]) * 2);
    }

    const uint32_t alnb = (uint32_t)((((lane & 7) + ((lane >> 3) & 1) * 8) * HSTR
                                     + ((lane >> 4) & 1) * 8) * 2);
    const uint32_t blnb = (uint32_t)(((((lane >> 4) & 1) * 8 + (lane & 7)) * HSTR
                                     + ((lane >> 3) & 1) * 8) * 2);

    const int KT = K >> 5;
    float keep[4][4][4];
    const int gset[3] = {0, 2, 3};

#pragma unroll 1
    for (int ph = 0; ph < 3; ++ph) {
        const int gate = gset[ph];
        const __half* Wb = W + ((size_t)(gate * HH + nb)) * K;

        float acc[4][4][4];
#pragma unroll
        for (int a = 0; a < 4; a++)
#pragma unroll
            for (int b = 0; b < 4; b++)
#pragma unroll
                for (int c = 0; c < 4; c++) acc[a][b][c] = 0.0f;

        auto issue = [&](int kt) {
            const int koff = kt * 32;
            const uint32_t so = (uint32_t)((kt & 3) * L4_ST * 2);
#pragma unroll
            for (int i = 0; i < 2; i++) cp16(adst[i] + so, aptr[i] + koff);
#pragma unroll
            for (int i = 0; i < 2; i++) cp16(bdst[i] + so, Wb + (size_t)brow[i] * K + bkc[i] + koff);
            cp_commit();
        };

        const int pre = KT < 3 ? KT : 3;
        for (int s = 0; s < pre; ++s) issue(s);

        for (int kt = 0; kt < KT; ++kt) {
            if (kt < KT - 2)       asm volatile("cp.async.wait_group 2;");
            else if (kt == KT - 2) asm volatile("cp.async.wait_group 1;");
            else                   asm volatile("cp.async.wait_group 0;");
            __syncthreads();
            if (kt + 3 < KT) issue(kt + 3);

            const uint32_t sb = smb + (uint32_t)((kt & 3) * L4_ST * 2);
#pragma unroll
            for (int kk = 0; kk < 32; kk += 16) {
                uint32_t af[4][4], bfr[4][2];
#pragma unroll
                for (int mt = 0; mt < 4; mt++) {
                    const uint32_t ad = sb + (uint32_t)(((wm * 64 + mt * 16) * HSTR + kk) * 2) + alnb;
                    ldsm_x4(af[mt][0], af[mt][1], af[mt][2], af[mt][3], ad);
                }
#pragma unroll
                for (int np = 0; np < 2; np++) {
                    const uint32_t bd = sb + (uint32_t)(((128 + wn * 32 + np * 16) * HSTR + kk) * 2) + blnb;
                    ldsm_x4(bfr[np * 2][0], bfr[np * 2][1], bfr[np * 2 + 1][0], bfr[np * 2 + 1][1], bd);
                }
#pragma unroll
                for (int mt = 0; mt < 4; mt++)
#pragma unroll
                    for (int nt = 0; nt < 4; nt++)
                        mma_fp16(acc[mt][nt], af[mt][0], af[mt][1], af[mt][2], af[mt][3],
                                 bfr[nt][0], bfr[nt][1]);
            }
        }
        __syncthreads();

#pragma unroll
        for (int mt = 0; mt < 4; mt++) {
#pragma unroll
            for (int nt = 0; nt < 4; nt++) {
                const int gcol = gate * HH + nb + wn * 32 + nt * 8 + 2 * q;
                const float b0 = bih[gcol] + bhh[gcol];
                const float b1 = bih[gcol + 1] + bhh[gcol + 1];
                const float u0 = acc[mt][nt][0] + b0, u1 = acc[mt][nt][1] + b1;
                const float u2 = acc[mt][nt][2] + b0, u3 = acc[mt][nt][3] + b1;
                if (ph == 0) {
                    const float2 sa = sig2(u0, u1), sb2 = sig2(u2, u3);
                    keep[mt][nt][0] = sa.x; keep[mt][nt][1] = sa.y;
                    keep[mt][nt][2] = sb2.x; keep[mt][nt][3] = sb2.y;
                } else if (ph == 1) {
                    const float2 ta = tanh2f(u0, u1), tb = tanh2f(u2, u3);
                    keep[mt][nt][0] *= ta.x; keep[mt][nt][1] *= ta.y;
                    keep[mt][nt][2] *= tb.x; keep[mt][nt][3] *= tb.y;
                } else {
                    const float2 sa = sig2(u0, u1), sb2 = sig2(u2, u3);
                    const float2 ka = tanh2f(keep[mt][nt][0], keep[mt][nt][1]);
                    const float2 kb = tanh2f(keep[mt][nt][2], keep[mt][nt][3]);
                    const int row0 = mb + wm * 64 + mt * 16 + g;
                    const int colh = nb + wn * 32 + nt * 8 + 2 * q;
                    if (row0 < M)
                        *(__half2*)(Hout + (size_t)row0 * HH + colh) =
                            __floats2half2_rn(sa.x * ka.x, sa.y * ka.y);
                    if (row0 + 8 < M)
                        *(__half2*)(Hout + (size_t)(row0 + 8) * HH + colh) =
                            __floats2half2_rn(sb2.x * kb.x, sb2.y * kb.y);
                }
            }
        }
    }
}

// ------------------------- 128-CTA grid barrier (acq_rel) ---------------------
__device__ __forceinline__ void grid_bar()
{
    __syncthreads();
    if (threadIdx.x == 0) {
        const unsigned gen = ld_acquire(&g_sense);
        const unsigned arrived = atom_add_acqrel(&g_cnt, 1u);
        if (arrived == 127u) {
            g_cnt = 0;
            atom_add_acqrel(&g_sense, 1u);
        } else {
            while (ld_acquire(&g_sense) == gen) { __nanosleep(16); }
        }
    }
    __syncthreads();
}

// =============================================================================
// FUSED DUAL-LAYER RECURRENCE — R15 structure + xg prefetch hoisted before the
// barrier (overlaps xg DRAM latency with barrier wait).
// =============================================================================
__launch_bounds__(256, 1)
__global__ void fused_recur_kernel(const __half* __restrict__ xg1,  // [BT,4096] fp16
                                   const float* __restrict__ Whh1,
                                   const float* __restrict__ Wih2,
                                   const float* __restrict__ Whh2,
                                   const float* __restrict__ b2i,
                                   const float* __restrict__ b2h,
                                   __half* __restrict__ hlast,
                                   __half* __restrict__ h1F,
                                   __half* __restrict__ h2F)
{
    extern __shared__ char smc[];
    __half* slab = (__half*)smc;                 // 3 x [32][1032]
    float*  PIg  = (float*)(smc + F_G_B);        // [4 warps][32 lanes][16]

    const int tid = threadIdx.x, lane = tid & 31, warp = tid >> 5;
    const int g = lane >> 2, q = lane & 3;
    const int n0 = blockIdx.x * 8;

#pragma unroll 1
    for (int c = 0; c < 96; c++) {
        const float* Wsrc = (c < 32) ? Whh1 : (c < 64) ? Wih2 : Whh2;
        const int rr = c & 31;
        const int row = (rr >> 3) * HH + n0 + (rr & 7);
        const float4 v = *(const float4*)(Wsrc + (size_t)row * HH + tid * 4);
        __half* d = slab + c * FW_STR + tid * 4;
        d[0] = __float2half_rn(v.x); d[1] = __float2half_rn(v.y);
        d[2] = __float2half_rn(v.z); d[3] = __float2half_rn(v.w);
    }
    __syncthreads();

    const __half* Ws1 = slab;
    const __half* Wi2 = slab + 32 * FW_STR;
    const __half* Ws2 = slab + 64 * FW_STR;

    const int mq = warp & 3;
    const int isL = (warp < 4);
    const __half* bA[4]; const __half* bB[4];
#pragma unroll
    for (int nt = 0; nt < 4; nt++) {
        const int n = nt * 8 + g;
        bA[nt] = (isL ? Ws1 : Ws2) + n * FW_STR + 2 * q;
        bB[nt] = Wi2 + n * FW_STR + 2 * q;
    }

    const int row_a = mq * 16 + g, row_b = row_a + 8;
    const int colj = n0 + 2 * q;
    const size_t st_off = ((size_t)(mq * 64 + (blockIdx.x >> 1)) * 32 + lane) * 8
                          + 4 * (size_t)(blockIdx.x & 1);

    float bias_[4][2];
    if (!isL) {
#pragma unroll
        for (int gg = 0; gg < 4; gg++) {
            const float2 bi = *(const float2*)(b2i + gg * HH + colj);
            const float2 bh = *(const float2*)(b2h + gg * HH + colj);
            bias_[gg][0] = bi.x + bh.x;
            bias_[gg][1] = bi.y + bh.y;
        }
    }

    float c00 = 0.f, c01 = 0.f, c10 = 0.f, c11 = 0.f;

    // xg prefetch registers (loaded one step ahead, before the barrier)
    float xgv[4][4];
    if (isL) {
        const size_t ba = ((size_t)(row_a * TT + 0)) * G4 + colj;
        const size_t bb = ((size_t)(row_b * TT + 0)) * G4 + colj;
#pragma unroll
        for (int gg = 0; gg < 4; gg++) {
            const float2 fa = __half22float2(*(const __half2*)(xg1 + ba + gg * 1024));
            const float2 fb = __half22float2(*(const __half2*)(xg1 + bb + gg * 1024));
            xgv[gg][0] = fa.x; xgv[gg][1] = fa.y;
            xgv[gg][2] = fb.x; xgv[gg][3] = fb.y;
        }
    }

#pragma unroll 1
    for (int s = 0; s <= TT; s++) {
        float accA[4][4], accB[4][4];
#pragma unroll
        for (int nt = 0; nt < 4; nt++)
#pragma unroll
            for (int cc = 0; cc < 4; cc++) { accA[nt][cc] = 0.f; accB[nt][cc] = 0.f; }

        const int doA = isL ? (s >= 1) : (s >= 2);
        if (doA) {
            const int par = (s - 1) & 1;
            const float4* Ab = (const float4*)((isL ? h1F : h2F) + (size_t)par * 65536)
                               + (size_t)mq * 64 * 32 + lane;

            float4 buf[8];
#pragma unroll
            for (int p = 0; p < 8; p++) buf[p] = __ldcg(Ab + p * 32);

#pragma unroll 8
            for (int kk = 0; kk < 64; ++kk) {
                const float4 f = buf[kk & 7];
                if (kk < 56) buf[kk & 7] = __ldcg(Ab + (kk + 8) * 32);
                const uint32_t a0 = __float_as_uint(f.x), a1 = __float_as_uint(f.y);
                const uint32_t a2 = __float_as_uint(f.z), a3 = __float_as_uint(f.w);
#pragma unroll
                for (int nt = 0; nt < 4; nt++) {
                    const uint32_t bb0 = ld_u32h(bA[nt] + kk * 16);
                    const uint32_t bb1 = ld_u32h(bA[nt] + kk * 16 + 8);
                    mma_fp16(accA[nt], a0, a1, a2, a3, bb0, bb1);
                }
                if (isL) {
#pragma unroll
                    for (int nt = 0; nt < 4; nt++) {
                        const uint32_t bb0 = ld_u32h(bB[nt] + kk * 16);
                        const uint32_t bb1 = ld_u32h(bB[nt] + kk * 16 + 8);
                        mma_fp16(accB[nt], a0, a1, a2, a3, bb0, bb1);
                    }
                }
            }

            if (isL) {
                float* pw = PIg + (mq * 32 + lane) * 16;
#pragma unroll
                for (int nt = 0; nt < 4; nt++)
                    *(float4*)(pw + nt * 4) = make_float4(accB[nt][0], accB[nt][1],
                                                          accB[nt][2], accB[nt][3]);
            }
        }

        if (isL && s < TT) {
            const float gi0 = xgv[0][0] + accA[0][0], gi1 = xgv[0][1] + accA[0][1];
            const float gi2 = xgv[0][2] + accA[0][2], gi3 = xgv[0][3] + accA[0][3];
            const float gf0 = xgv[1][0] + accA[1][0], gf1 = xgv[1][1] + accA[1][1];
            const float gf2 = xgv[1][2] + accA[1][2], gf3 = xgv[1][3] + accA[1][3];
            const float gG0 = xgv[2][0] + accA[2][0], gG1 = xgv[2][1] + accA[2][1];
            const float gG2 = xgv[2][2] + accA[2][2], gG3 = xgv[2][3] + accA[2][3];
            const float go0 = xgv[3][0] + accA[3][0], go1 = xgv[3][1] + accA[3][1];
            const float go2 = xgv[3][2] + accA[3][2], go3 = xgv[3][3] + accA[3][3];
            const float2 si01 = sig2(gi0, gi1), si23 = sig2(gi2, gi3);
            const float2 sf01 = sig2(gf0, gf1), sf23 = sig2(gf2, gf3);
            const float2 tg01 = tanh2f(gG0, gG1), tg23 = tanh2f(gG2, gG3);
            const float2 so01 = sig2(go0, go1), so23 = sig2(go2, go3);
            c00 = fmaf(sf01.x, c00, si01.x * tg01.x);
            c01 = fmaf(sf01.y, c01, si01.y * tg01.y);
            c10 = fmaf(sf23.x, c10, si23.x * tg23.x);
            c11 = fmaf(sf23.y, c11, si23.y * tg23.y);
            const float2 tc01 = tanh2f(c00, c01), tc23 = tanh2f(c10, c11);
            const __half2 lo = __floats2half2_rn(so01.x * tc01.x, so01.y * tc01.y);
            const __half2 hi = __floats2half2_rn(so23.x * tc23.x, so23.y * tc23.y);
            uint2 val;
            val.x = *(const uint32_t*)&lo;
            val.y = *(const uint32_t*)&hi;
            *(uint2*)(h1F + (size_t)(s & 1) * 65536 + st_off) = val;
        }

        __syncthreads();

        if (!isL && s >= 1) {
            const float* pw = PIg + (mq * 32 + lane) * 16;
            float pi[4][4];
#pragma unroll
            for (int nt = 0; nt < 4; nt++) {
                const float4 v = *(const float4*)(pw + nt * 4);
                pi[nt][0] = v.x; pi[nt][1] = v.y; pi[nt][2] = v.z; pi[nt][3] = v.w;
            }
            const float gi0 = pi[0][0] + bias_[0][0] + accA[0][0];
            const float gi1 = pi[0][1] + bias_[0][1] + accA[0][1];
            const float gi2 = pi[0][2] + bias_[0][0] + accA[0][2];
            const float gi3 = pi[0][3] + bias_[0][1] + accA[0][3];
            const float gf0 = pi[1][0] + bias_[1][0] + accA[1][0];
            const float gf1 = pi[1][1] + bias_[1][1] + accA[1][1];
            const float gf2 = pi[1][2] + bias_[1][0] + accA[1][2];
            const float gf3 = pi[1][3] + bias_[1][1] + accA[1][3];
            const float gG0 = pi[2][0] + bias_[2][0] + accA[2][0];
            const float gG1 = pi[2][1] + bias_[2][1] + accA[2][1];
            const float gG2 = pi[2][2] + bias_[2][0] + accA[2][2];
            const float gG3 = pi[2][3] + bias_[2][1] + accA[2][3];
            const float go0 = pi[3][0] + bias_[3][0] + accA[3][0];
            const float go1 = pi[3][1] + bias_[3][1] + accA[3][1];
            const float go2 = pi[3][2] + bias_[3][0] + accA[3][2];
            const float go3 = pi[3][3] + bias_[3][1] + accA[3][3];
            const float2 si01 = sig2(gi0, gi1), si23 = sig2(gi2, gi3);
            const float2 sf01 = sig2(gf0, gf1), sf23 = sig2(gf2, gf3);
            const float2 tg01 = tanh2f(gG0, gG1), tg23 = tanh2f(gG2, gG3);
            const float2 so01 = sig2(go0, go1), so23 = sig2(go2, go3);
            c00 = fmaf(sf01.x, c00, si01.x * tg01.x);
            c01 = fmaf(sf01.y, c01, si01.y * tg01.y);
            c10 = fmaf(sf23.x, c10, si23.x * tg23.x);
            c11 = fmaf(sf23.y, c11, si23.y * tg23.y);
            const float2 tc01 = tanh2f(c00, c01), tc23 = tanh2f(c10, c11);
            const float h0 = so01.x * tc01.x, h1 = so01.y * tc01.y;
            const float h2 = so23.x * tc23.x, h3 = so23.y * tc23.y;
            if (s < TT) {
                const __half2 lo = __floats2half2_rn(h0, h1);
                const __half2 hi = __floats2half2_rn(h2, h3);
                uint2 val;
                val.x = *(const uint32_t*)&lo;
                val.y = *(const uint32_t*)&hi;
                *(uint2*)(h2F + (size_t)(s & 1) * 65536 + st_off) = val;
            } else {
                *(__half2*)(hlast + (size_t)row_a * HH + colj) = __floats2half2_rn(h0, h1);
                *(__half2*)(hlast + (size_t)row_b * HH + colj) = __floats2half2_rn(h2, h3);
            }
        }

        // hoisted xg prefetch for step s+1 (overlaps the barrier wait)
        if (isL && s + 1 < TT) {
            const size_t ba = ((size_t)(row_a * TT + (s + 1))) * G4 + colj;
            const size_t bb = ((size_t)(row_b * TT + (s + 1))) * G4 + colj;
#pragma unroll
            for (int gg = 0; gg < 4; gg++) {
                const float2 fa = __half22float2(*(const __half2*)(xg1 + ba + gg * 1024));
                const float2 fb = __half22float2(*(const __half2*)(xg1 + bb + gg * 1024));
                xgv[gg][0] = fa.x; xgv[gg][1] = fa.y;
                xgv[gg][2] = fb.x; xgv[gg][3] = fb.y;
            }
        }

        if (s < TT) grid_bar();
    }
}

// ------------------------- final MLP layer 3 ---------------------------------
__global__ void mlp3_kernel(const __half* __restrict__ z2, const float* __restrict__ W3,
                            const float* __restrict__ b3, float* __restrict__ out)
{
    __shared__ float red[8];
    const int b = blockIdx.x;
    float s = 0.f;
    for (int k = threadIdx.x; k < 512; k += 256)
        s += __half2float(z2[b * 512 + k]) * W3[k];
#pragma unroll
    for (int o = 16; o; o >>= 1) s += __shfl_down_sync(0xffffffffu, s, o);
    if ((threadIdx.x & 31) == 0) red[threadIdx.x >> 5] = s;
    __syncthreads();
    if (threadIdx.x < 8) {
        s = red[threadIdx.x];
#pragma unroll
        for (int o = 4; o; o >>= 1) s += __shfl_down_sync(0xffu, s, o);
        if (threadIdx.x == 0) out[b] = s + b3[0];
    }
}

// ------------------------- launcher ------------------------------------------
extern "C" void kernel_launch(void* const* d_in, const int* in_sizes, int n_in,
                              void* d_out, int out_size)
{
    const float* xx       = (const float*)d_in[0];
    const float* l1_Wih0  = (const float*)d_in[1];
    const float* l1_bih0  = (const float*)d_in[2];
    const float* l1_bhh0  = (const float*)d_in[3];
    const float* l1_Wih1  = (const float*)d_in[4];
    const float* l1_bih1  = (const float*)d_in[5];
    const float* l1_bhh1  = (const float*)d_in[6];
    const float* l2_Wih0  = (const float*)d_in[7];
    const float* l2_Whh0  = (const float*)d_in[8];
    const float* l2_bih0  = (const float*)d_in[9];
    const float* l2_bhh0  = (const float*)d_in[10];
    const float* l2_Wih1  = (const float*)d_in[11];
    const float* l2_Whh1  = (const float*)d_in[12];
    const float* l2_bih1  = (const float*)d_in[13];
    const float* l2_bhh1  = (const float*)d_in[14];
    const float* mlp_W1   = (const float*)d_in[15];
    const float* mlp_b1   = (const float*)d_in[16];
    const float* mlp_W2   = (const float*)d_in[17];
    const float* mlp_b2   = (const float*)d_in[18];
    const float* mlp_W3   = (const float*)d_in[19];
    const float* mlp_b3   = (const float*)d_in[20];
    float* out = (float*)d_out;

    void* p;
    cudaGetSymbolAddress(&p, g_gates16); __half* gates16 = (__half*)p;
    cudaGetSymbolAddress(&p, g_w16);   __half* w16   = (__half*)p;
    cudaGetSymbolAddress(&p, g_h1);    __half* h1    = (__half*)p;
    cudaGetSymbolAddress(&p, g_h2);    __half* h2    = (__half*)p;
    cudaGetSymbolAddress(&p, g_h1F);   __half* h1F   = (__half*)p;
    cudaGetSymbolAddress(&p, g_h2F);   __half* h2F   = (__half*)p;
    cudaGetSymbolAddress(&p, g_hlast); __half* hlast = (__half*)p;
    cudaGetSymbolAddress(&p, g_z1);    __half* z1    = (__half*)p;
    cudaGetSymbolAddress(&p, g_z2);    __half* z2    = (__half*)p;

    const int lstm1_smem  = 4 * L4_ST * 2;    // 81920 B (4-stage, 1 CTA/SM)
    const int gemm_smem   = 3 * L_ST * 2;     // 61440 B (3-stage, 2 CTA/SM)
    const int fused_smem  = F_SMEM_B;         // 206336 B
    cudaFuncSetAttribute((const void*)gemm128_kernel<0,1>, cudaFuncAttributeMaxDynamicSharedMemorySize, gemm_smem);
    cudaFuncSetAttribute((const void*)gemm128_kernel<1,1>, cudaFuncAttributeMaxDynamicSharedMemorySize, gemm_smem);
    cudaFuncSetAttribute((const void*)lstm1_16_kernel,     cudaFuncAttributeMaxDynamicSharedMemorySize, lstm1_smem);
    cudaFuncSetAttribute((const void*)fused_recur_kernel,  cudaFuncAttributeMaxDynamicSharedMemorySize, fused_smem);

    const dim3 blk(256);

    // [0] fp32 -> fp16 (xx + 6 weight matrices)
    convert_kernel<<<4849664 / 256, blk>>>(xx, l1_Wih0, l1_Wih1, l2_Wih0, l2_Wih1, mlp_W1, mlp_W2);

    // [1][2] lstm1 (fused, f gate skipped)
    lstm1_16_kernel<<<dim3(HH / 128, BT / 128), blk, lstm1_smem>>>(w16 + X16_OFF, 256, w16 + W_L1A,
                                                                   l1_bih0, l1_bhh0, h1, BT, 256);
    lstm1_16_kernel<<<dim3(HH / 128, BT / 128), blk, lstm1_smem>>>(h1, HH, w16 + W_L1B,
                                                                   l1_bih1, l1_bhh1, h2, BT, HH);

    // [3] lstm2 layer-0 xg GEMM (fp16 out, 2 CTA/SM) ; [4] fused dual recurrence
    gemm128_kernel<0,1><<<dim3(G4 / 128, BT / 128), blk, gemm_smem>>>(h2, HH, w16 + W_L2A,
                                                                      l2_bih0, l2_bhh0,
                                                                      gates16, BT, G4, HH);
    fused_recur_kernel<<<128, blk, fused_smem>>>(gates16, l2_Whh0, l2_Wih1, l2_Whh1,
                                                 l2_bih1, l2_bhh1, hlast, h1F, h2F);

    // [5][6][7] MLP on h2(255)
    gemm128_kernel<1,1><<<dim3(HH / 128, 1), blk, gemm_smem>>>(hlast, HH, w16 + W_M1, mlp_b1, nullptr,
                                                               z1, BB, HH, HH);
    gemm128_kernel<1,1><<<dim3((HH / 2) / 128, 1), blk, gemm_smem>>>(z1, HH, w16 + W_M2, mlp_b2, nullptr,
                                                                     z2, BB, HH / 2, HH);
    mlp3_kernel<<<BB, blk>>>(z2, mlp_W3, mlp_b3, out);
}